// round 1
// baseline (speedup 1.0000x reference)
#include <cuda_runtime.h>

#define WH   128
#define NPIX (WH*WH)      // 16384
#define NB   2            // batch
#define NK   16           // instances
#define NBK  (NB*NK)      // 32

// Scratch (no allocations allowed): G2 then d (in-place, row-granular).
__device__ float    g_scr[NBK * NPIX];   // 2 MB
__device__ unsigned g_max[NBK];          // per-(b,k) max(d) as ordered uint
__device__ float    g_part[128];         // per-block loss partials

// ---------------------------------------------------------------------------
// K1: column-wise 1D EDT -> G2[bk,i,j] = min_{i': bg} (i-i')^2  (1e9 if none)
// One block per (b,k); thread j owns column j. Also resets g_max.
// ---------------------------------------------------------------------------
__global__ void k_g2(const int* __restrict__ mask)
{
    const int bk = blockIdx.x;            // 0..31
    const int b  = bk >> 4;
    const int k  = (bk & 15) + 1;
    const int j  = threadIdx.x;           // 0..127

    if (j == 0) g_max[bk] = 0u;

    __shared__ unsigned char s_fd[NPIX];  // forward distances (capped 255)

    const int* mcol = mask + b * NPIX + j;
    float* gout = g_scr + bk * NPIX + j;

    // forward scan (top -> bottom): distance to nearest bg above/at
    int cur = 255;
    for (int i = 0; i < WH; i++) {
        bool nuc = (mcol[i * WH] == k);
        cur = nuc ? min(cur + 1, 255) : 0;
        s_fd[i * WH + j] = (unsigned char)cur;
    }
    // backward scan + combine
    cur = 255;
    for (int i = WH - 1; i >= 0; i--) {
        bool nuc = (mcol[i * WH] == k);
        cur = nuc ? min(cur + 1, 255) : 0;
        int mind = min(cur, (int)s_fd[i * WH + j]);
        gout[i * WH] = (mind >= WH) ? 1e9f : (float)(mind * mind);
    }
}

// ---------------------------------------------------------------------------
// K2: row-wise envelope (brute force, exact):
//   d[i,j] = sqrt( min_{j'} G2[i,j'] + (j-j')^2 ),  in-place over g_scr.
// One block per (bk, row i); thread j owns pixel (i,j). Block-max -> g_max.
// ---------------------------------------------------------------------------
__global__ void k_d2()
{
    const int blk = blockIdx.x;           // 0..4095
    const int bk  = blk >> 7;
    const int i   = blk & 127;
    const int j   = threadIdx.x;

    __shared__ float row[WH];
    float* gp = g_scr + (bk * WH + i) * WH;
    row[j] = gp[j];
    __syncthreads();

    const float fj = (float)j;
    float m = 1e30f;
#pragma unroll
    for (int jp = 0; jp < WH; jp++) {
        float t = fj - (float)jp;         // t^2 exact integer -> fmaf == add
        m = fminf(m, fmaf(t, t, row[jp]));
    }
    float d = __fsqrt_rn(m);              // IEEE sqrt regardless of fast-math
    gp[j] = d;

    // block max reduction (d >= 0, so uint ordering == float ordering)
    float mx = d;
#pragma unroll
    for (int off = 16; off; off >>= 1)
        mx = fmaxf(mx, __shfl_xor_sync(0xFFFFFFFFu, mx, off));
    __shared__ float wmax[4];
    if ((j & 31) == 0) wmax[j >> 5] = mx;
    __syncthreads();
    if (j == 0) {
        float mm = fmaxf(fmaxf(wmax[0], wmax[1]), fmaxf(wmax[2], wmax[3]));
        atomicMax(&g_max[bk], __float_as_uint(mm));
    }
}

// ---------------------------------------------------------------------------
// K3: normalize+threshold+bin, write gt (8 channels/pixel), smooth-L1 loss
// partials. 128 blocks x 256 threads over 32768 pixels. Deterministic:
// per-block partial -> g_part (no float atomics).
// ---------------------------------------------------------------------------
__global__ void k_final(const float* __restrict__ pred,
                        const int*   __restrict__ mask,
                        const float* __restrict__ ign,
                        float* __restrict__ out)
{
    const int p  = blockIdx.x * blockDim.x + threadIdx.x;  // 0..32767
    const int b  = p >> 14;
    const int xy = p & (NPIX - 1);

    int c0 = -1;
    const int lab = mask[p];
    if (lab > 0) {
        const int bk = b * 16 + (lab - 1);
        float d  = g_scr[bk * NPIX + xy];
        float mv = __uint_as_float(g_max[bk]);
        float dn = (mv > 0.f) ? __fdiv_rn(d, mv) : d;   // IEEE div
        if (dn < 0.5f) dn = 0.0f;
        if (dn > 0.7f) dn = 1.0f;
        const float DDD[8] = {0.83f, 0.68f, 0.54f, 0.41f, 0.29f, 0.18f, 0.09f, 0.0f};
        c0 = 7;
#pragma unroll
        for (int c = 0; c < 8; c++) {
            if (dn >= DDD[c]) { c0 = c; break; }   // == [DDD[c], DDD[c-1]) test
        }
    }

    const float* pp = pred + b * 8 * NPIX + xy;
    float*       go = out + 1 + b * 8 * NPIX + xy;   // out[0] = loss
    float s = 0.f;
#pragma unroll
    for (int c = 0; c < 8; c++) {
        float g = (c == c0) ? 1.f : 0.f;
        go[c * NPIX] = g;
        float diff = pp[c * NPIX] - g;
        float ad = fabsf(diff);
        s += (ad < 1.f) ? 0.5f * diff * diff : (ad - 0.5f);
    }
    float contrib = ign[p] * s * 0.125f;   // mean over C=8

    // block reduction
#pragma unroll
    for (int off = 16; off; off >>= 1)
        contrib += __shfl_xor_sync(0xFFFFFFFFu, contrib, off);
    __shared__ float ws[8];
    const int tid = threadIdx.x;
    if ((tid & 31) == 0) ws[tid >> 5] = contrib;
    __syncthreads();
    if (tid == 0) {
        float t = 0.f;
#pragma unroll
        for (int w = 0; w < 8; w++) t += ws[w];
        g_part[blockIdx.x] = t;
    }
}

// ---------------------------------------------------------------------------
// K4: deterministic final reduction of 128 partials -> out[0]
// ---------------------------------------------------------------------------
__global__ void k_sum(float* __restrict__ out)
{
    const int tid = threadIdx.x;   // 128 threads
    float v = g_part[tid];
#pragma unroll
    for (int off = 16; off; off >>= 1)
        v += __shfl_xor_sync(0xFFFFFFFFu, v, off);
    __shared__ float ws[4];
    if ((tid & 31) == 0) ws[tid >> 5] = v;
    __syncthreads();
    if (tid == 0) {
        float t = (ws[0] + ws[1]) + (ws[2] + ws[3]);
        out[0] = t * (1.f / (float)(NB * NPIX));   // mean over B*W*H
    }
}

extern "C" void kernel_launch(void* const* d_in, const int* in_sizes, int n_in,
                              void* d_out, int out_size)
{
    const float* pred = (const float*)d_in[0];   // [2,8,128,128] f32
    const int*   mask = (const int*)  d_in[1];   // [2,128,128]   i32
    const float* ign  = (const float*)d_in[2];   // [2,128,128]   f32
    float* out = (float*)d_out;                  // [0]=loss, [1..]=gt [2,8,128,128]

    k_g2   <<<NBK,        128>>>(mask);
    k_d2   <<<NBK * WH,   128>>>();
    k_final<<<(NB*NPIX)/256, 256>>>(pred, mask, ign, out);
    k_sum  <<<1,          128>>>(out);
}

// round 2
// speedup vs baseline: 1.1863x; 1.1863x over previous
#include <cuda_runtime.h>

#define WH    128
#define NPIX  (WH*WH)      // 16384
#define NB    2
#define NBK   32           // 2 batches x 16 instances
#define NBLK  128          // persistent grid: must all be co-resident (<=148 SMs)
#define TPB   256

// Scratch (no allocations allowed)
__device__ float    g_scr[NBK * NPIX];   // G2 (column-pass squared distances), 2 MB
__device__ unsigned g_max[NBK];          // per-(b,k) max(d) as ordered uint
__device__ float    g_part[NBLK];        // per-block loss partials
__device__ unsigned g_count = 0;         // monotonic grid-barrier ticket counter

// ---------------------------------------------------------------------------
// Grid-wide barrier: monotonic ticket counter, safe across graph replays
// (never reset; all NBLK blocks guaranteed resident).
// ---------------------------------------------------------------------------
__device__ __forceinline__ void gridbar()
{
    __threadfence();                     // release: publish our writes
    __syncthreads();
    if (threadIdx.x == 0) {
        unsigned ticket = atomicAdd(&g_count, 1u) + 1u;
        unsigned target = ((ticket + NBLK - 1u) / NBLK) * NBLK;
        volatile unsigned* vc = &g_count;
        while (*vc < target) __nanosleep(20);
    }
    __syncthreads();
    __threadfence();                     // acquire side
}

__global__ __launch_bounds__(TPB, 1) void fused_kernel(
    const float* __restrict__ pred,
    const int*   __restrict__ mask,
    const float* __restrict__ ign,
    float* __restrict__ out)
{
    const int tid = threadIdx.x;
    const int bx  = blockIdx.x;

    // ======================= Phase 1: column-wise 1D EDT =====================
    // G2[bk,i,j] = min_{i' : bg} (i-i')^2  (1e9 if none). 4096 column tasks,
    // 32 per block (warp 0), coalesced mask loads across lanes (consecutive j).
    if (bx == 0 && tid >= 224) g_max[tid - 224] = 0u;   // reset 32 maxima

    if (tid < 32) {
        const int t  = bx * 32 + tid;        // 0..4095
        const int bk = t >> 7;
        const int j  = t & 127;
        const int b  = bk >> 4;
        const int k  = (bk & 15) + 1;
        const int* mcol = mask + b * NPIX + j;
        float*     gcol = g_scr + bk * NPIX + j;

        int cur = WH;                        // >=128 means "no bg yet"
        #pragma unroll 8
        for (int i = 0; i < WH; i++) {
            cur = (mcol[i * WH] == k) ? (cur + 1) : 0;
            gcol[i * WH] = (float)cur;       // stage forward distance
        }
        cur = WH;
        #pragma unroll 8
        for (int i = WH - 1; i >= 0; i--) {
            cur = (mcol[i * WH] == k) ? (cur + 1) : 0;
            int fw = (int)gcol[i * WH];
            int md = min(fw, cur);
            gcol[i * WH] = (md >= WH) ? 1e9f : (float)(md * md);
        }
    }

    gridbar();

    // ======================= Phase 2: row envelope at own pixel ==============
    // d(p) = sqrt( min_{j'} G2[bk(p), i(p), j'] + (j-j')^2 ), only for the
    // pixel's OWN label (bins are masked by nuclei; d=0 elsewhere; per-(b,k)
    // max is attained on nuclei). G2 rows staged in shared, 129-stride padded.
    const int p      = bx * TPB + tid;       // pixel id 0..32767
    const int b      = p >> 14;
    const int xy     = p & (NPIX - 1);
    const int i0     = xy >> 7;
    const int j      = xy & 127;
    const int base_i = (bx & 63) * 2;        // first of the block's 2 rows

    __shared__ float    s_g2[16 * 2 * 129];  // 16 labels x 2 rows, padded
    __shared__ unsigned smax[16];
    __shared__ float    ws[8];

    for (int idx = tid; idx < 16 * 2 * WH; idx += TPB) {
        int kk = idx >> 8;                   // label-1
        int r  = (idx >> 7) & 1;             // which of the 2 rows
        int jp = idx & 127;
        s_g2[(kk * 2 + r) * 129 + jp] =
            g_scr[((b * 16 + kk) * WH + base_i + r) * WH + jp];
    }
    if (tid < 16) smax[tid] = 0u;
    __syncthreads();

    const int lab = mask[p];
    float d  = 0.f;
    int   bk = 0;
    if (lab > 0) {
        bk = (b << 4) + lab - 1;
        const float* row = s_g2 + ((lab - 1) * 2 + (i0 - base_i)) * 129;
        const float fj = (float)j;
        float m0 = 1e30f, m1 = 1e30f, m2 = 1e30f, m3 = 1e30f;
        #pragma unroll
        for (int q = 0; q < 32; q++) {
            float t0 = fj - (float)(4*q+0); m0 = fminf(m0, fmaf(t0, t0, row[4*q+0]));
            float t1 = fj - (float)(4*q+1); m1 = fminf(m1, fmaf(t1, t1, row[4*q+1]));
            float t2 = fj - (float)(4*q+2); m2 = fminf(m2, fmaf(t2, t2, row[4*q+2]));
            float t3 = fj - (float)(4*q+3); m3 = fminf(m3, fmaf(t3, t3, row[4*q+3]));
        }
        d = __fsqrt_rn(fminf(fminf(m0, m1), fminf(m2, m3)));   // IEEE sqrt
        atomicMax(&smax[lab - 1], __float_as_uint(d));          // d>=0: uint order ok
    }
    __syncthreads();
    if (tid < 16 && smax[tid]) atomicMax(&g_max[(b << 4) + tid], smax[tid]);

    gridbar();

    // ======================= Phase 3: bin + gt write + smooth-L1 =============
    int c0 = -1;
    if (lab > 0) {
        float mv = __uint_as_float(g_max[bk]);
        float dn = (mv > 0.f) ? __fdiv_rn(d, mv) : d;          // IEEE div
        if (dn < 0.5f) dn = 0.0f;
        if (dn > 0.7f) dn = 1.0f;
        const float DDD[8] = {0.83f, 0.68f, 0.54f, 0.41f, 0.29f, 0.18f, 0.09f, 0.0f};
        c0 = 7;
        #pragma unroll
        for (int c = 0; c < 8; c++)
            if (dn >= DDD[c]) { c0 = c; break; }               // == [DDD[c], hi[c]) test
    }

    const float* pp = pred + b * 8 * NPIX + xy;
    float*       go = out + 1 + b * 8 * NPIX + xy;             // out[0] = loss
    float s = 0.f;
    #pragma unroll
    for (int c = 0; c < 8; c++) {
        float g = (c == c0) ? 1.f : 0.f;
        go[c * NPIX] = g;
        float diff = pp[c * NPIX] - g;
        float ad = fabsf(diff);
        s += (ad < 1.f) ? 0.5f * diff * diff : (ad - 0.5f);
    }
    float contrib = ign[p] * s * 0.125f;                       // mean over C=8

    #pragma unroll
    for (int off = 16; off; off >>= 1)
        contrib += __shfl_xor_sync(0xFFFFFFFFu, contrib, off);
    if ((tid & 31) == 0) ws[tid >> 5] = contrib;
    __syncthreads();
    if (tid == 0) {
        float tsum = 0.f;
        #pragma unroll
        for (int w = 0; w < 8; w++) tsum += ws[w];
        g_part[bx] = tsum;
    }

    gridbar();

    // ======================= Phase 4: final deterministic reduction ==========
    if (bx == 0) {
        float v = 0.f;
        if (tid < NBLK) {
            v = g_part[tid];
            #pragma unroll
            for (int off = 16; off; off >>= 1)
                v += __shfl_xor_sync(0xFFFFFFFFu, v, off);
            if ((tid & 31) == 0) ws[tid >> 5] = v;
        }
        __syncthreads();
        if (tid == 0)
            out[0] = ((ws[0] + ws[1]) + (ws[2] + ws[3])) * (1.f / (float)(NB * NPIX));
    }
}

extern "C" void kernel_launch(void* const* d_in, const int* in_sizes, int n_in,
                              void* d_out, int out_size)
{
    const float* pred = (const float*)d_in[0];   // [2,8,128,128] f32
    const int*   mask = (const int*)  d_in[1];   // [2,128,128]   i32
    const float* ign  = (const float*)d_in[2];   // [2,128,128]   f32
    float* out = (float*)d_out;                  // [0]=loss, [1..]=gt

    fused_kernel<<<NBLK, TPB>>>(pred, mask, ign, out);
}

// round 3
// speedup vs baseline: 1.9044x; 1.6054x over previous
#include <cuda_runtime.h>

#define WH    128
#define NPIX  (WH*WH)      // 16384
#define NB    2
#define NBK   32           // 2 batches x 16 instances
#define NBLK  128          // persistent grid (all co-resident on 148 SMs)
#define TPB   256

// Scratch (no allocations allowed)
__device__ float    g_rm2[NB * NPIX];    // per-pixel own-label vertical dist^2 (128KB)
__device__ unsigned g_max[NBK];          // per-(b,k) max(d) as ordered uint
__device__ float    g_part[NBLK];        // per-block loss partials
__device__ unsigned g_count = 0;         // monotonic grid-barrier ticket counter
__device__ unsigned g_done  = 0;         // monotonic arrival counter (final reduce)

// Grid-wide barrier: monotonic ticket counter, safe across graph replays.
__device__ __forceinline__ void gridbar()
{
    __threadfence();
    __syncthreads();
    if (threadIdx.x == 0) {
        unsigned ticket = atomicAdd(&g_count, 1u) + 1u;
        unsigned target = ((ticket + NBLK - 1u) / NBLK) * NBLK;
        volatile unsigned* vc = &g_count;
        while (*vc < target) __nanosleep(20);
    }
    __syncthreads();
    __threadfence();
}

__global__ __launch_bounds__(TPB, 1) void fused_kernel(
    const float* __restrict__ pred,
    const int*   __restrict__ mask,
    const float* __restrict__ ign,
    float* __restrict__ out)
{
    const int tid = threadIdx.x;
    const int bx  = blockIdx.x;

    // Shared: phase-2 label table is the big consumer
    __shared__ float    s_v[2 * 16 * 129];      // 16.5 KB: v[row][label][j']
    __shared__ int      s_lab[2][WH];
    __shared__ int      s_m31[2][4], s_m0[2][4];
    __shared__ int      s_L[2][4],   s_M[2][4];
    __shared__ unsigned smax[16];
    __shared__ float    ws[8];
    __shared__ int      s_last;

    // ================= Phase 1: per-pixel vertical run distance ==============
    // rm2[b,i,j] = min(dist to nearest different-label pixel above, below)^2
    // (1e9 if the whole column is one label). Warp = 32 consecutive i of one
    // column; run lengths via ballot + clz/ffs; 4-segment carry fixup.
    {
        const int q    = bx * TPB + tid;      // 0..32767 = pixel id
        const int b    = q >> 14;
        const int rem  = q & (NPIX - 1);
        const int j    = rem >> 7;
        const int i    = rem & 127;
        const int lane = tid & 31;
        const int w    = (tid >> 5) & 3;      // segment within column
        const int col  = tid >> 7;            // 0/1: column slot in block

        if (bx == 0 && tid < 32) g_max[tid] = 0u;  // reset maxima (bar follows)

        const int m = mask[b * NPIX + i * WH + j];
        if (lane == 31) s_m31[col][w] = m;
        if (lane == 0)  s_m0[col][w]  = m;
        __syncthreads();

        int mprev = __shfl_up_sync(0xFFFFFFFFu, m, 1);
        if (lane == 0)  mprev = (w > 0) ? s_m31[col][w - 1] : -1;
        int mnext = __shfl_down_sync(0xFFFFFFFFu, m, 1);
        if (lane == 31) mnext = (w < 3) ? s_m0[col][w + 1] : -1;

        const bool e  = (i > 0)   && (m == mprev);   // continues run upward
        const bool eb = (i < 127) && (m == mnext);   // continues run downward
        const unsigned z  = ~__ballot_sync(0xFFFFFFFFu, e);
        const unsigned zv = ~__ballot_sync(0xFFFFFFFFu, eb);

        if (lane == 0) {
            s_L[col][w] = z  ? (__clz(z) + 1) : -1;  // run len ending at lane31
            s_M[col][w] = zv ? __ffs((int)zv) : -1;  // run len starting at lane0
        }
        __syncthreads();
        if (tid < 2) {                                // resolve carries, column tid
            int L = s_L[tid][0];                      // w=0 always resolved (e[0]=0)
            for (int u = 1; u < 4; u++) { int lv = s_L[tid][u]; L = (lv < 0) ? L + 32 : lv; s_L[tid][u] = L; }
            int M = s_M[tid][3];                      // w=3 always resolved (eb[31]=0)
            for (int u = 2; u >= 0; u--) { int mv = s_M[tid][u]; M = (mv < 0) ? M + 32 : mv; s_M[tid][u] = M; }
        }
        __syncthreads();

        const unsigned zb  = z  & (0xFFFFFFFFu >> (31 - lane));  // zeros at/below
        const unsigned zb2 = zv & (0xFFFFFFFFu << lane);         // zeros at/above
        const int cprev = s_L[col][(w > 0) ? w - 1 : 0];
        const int cnext = s_M[col][(w < 3) ? w + 1 : 3];
        const int r  = zb  ? (lane - (31 - __clz(zb)) + 1) : (lane + 1 + cprev);
        const int rb = zb2 ? (__ffs((int)zb2) - lane)      : (32 - lane + cnext);

        const int fw = (r  == i + 1)   ? 1000 : r;    // run reaches top -> INF
        const int bw = (rb == 128 - i) ? 1000 : rb;   // run reaches bottom -> INF
        const int md = min(fw, bw);
        g_rm2[b * NPIX + i * WH + j] = (md >= WH) ? 1e9f : (float)(md * md);
    }

    gridbar();

    // ================= Phase 2: row envelope + per-(b,k) max =================
    const int p  = bx * TPB + tid;            // pixel id, row-major mapping
    const int b  = p >> 14;
    const int xy = p & (NPIX - 1);
    const int j  = xy & 127;
    const int r0 = tid >> 7;                  // which of the block's 2 rows
    const int base_i = (bx & 63) * 2;

    // Stage 2 rows of labels + rm2; build per-label table v[k][j'].
    {
        const int rr = tid >> 7, jp = tid & 127;
        const int gidx = b * NPIX + (base_i + rr) * WH + jp;
        const int lb = mask[gidx];
        const float rv = g_rm2[gidx];
        s_lab[rr][jp] = lb;
        float* vb = s_v + (rr * 16) * 129 + jp;
        #pragma unroll
        for (int k = 1; k <= 16; k++)
            vb[(k - 1) * 129] = (lb == k) ? rv : 0.f;
    }
    if (tid < 16) smax[tid] = 0u;
    __syncthreads();

    const int lab = s_lab[r0][j];
    float d = 0.f;
    int bk = 0;
    if (lab > 0) {
        bk = (b << 4) + lab - 1;
        const float* row = s_v + (r0 * 16 + lab - 1) * 129;
        const float fj = (float)j;
        float m0 = 1e30f, m1 = 1e30f, m2 = 1e30f, m3 = 1e30f;
        #pragma unroll
        for (int q = 0; q < 32; q++) {
            float t0 = fj - (float)(4*q+0); m0 = fminf(m0, fmaf(t0, t0, row[4*q+0]));
            float t1 = fj - (float)(4*q+1); m1 = fminf(m1, fmaf(t1, t1, row[4*q+1]));
            float t2 = fj - (float)(4*q+2); m2 = fminf(m2, fmaf(t2, t2, row[4*q+2]));
            float t3 = fj - (float)(4*q+3); m3 = fminf(m3, fmaf(t3, t3, row[4*q+3]));
        }
        d = __fsqrt_rn(fminf(fminf(m0, m1), fminf(m2, m3)));
        atomicMax(&smax[lab - 1], __float_as_uint(d));  // d>=0: uint order == float
    }
    __syncthreads();
    if (tid < 16 && smax[tid]) atomicMax(&g_max[(b << 4) + tid], smax[tid]);

    gridbar();

    // ================= Phase 3: bin + gt write + smooth-L1 ===================
    int c0 = -1;
    if (lab > 0) {
        float mv = __uint_as_float(g_max[bk]);
        float dn = (mv > 0.f) ? __fdiv_rn(d, mv) : d;
        if (dn < 0.5f) dn = 0.0f;
        if (dn > 0.7f) dn = 1.0f;
        const float DDD[8] = {0.83f, 0.68f, 0.54f, 0.41f, 0.29f, 0.18f, 0.09f, 0.0f};
        c0 = 7;
        #pragma unroll
        for (int c = 0; c < 8; c++)
            if (dn >= DDD[c]) { c0 = c; break; }
    }

    const float* pp = pred + b * 8 * NPIX + xy;
    float*       go = out + 1 + b * 8 * NPIX + xy;    // out[0] = loss
    float s = 0.f;
    #pragma unroll
    for (int c = 0; c < 8; c++) {
        float g = (c == c0) ? 1.f : 0.f;
        go[c * NPIX] = g;
        float diff = pp[c * NPIX] - g;
        float ad = fabsf(diff);
        s += (ad < 1.f) ? 0.5f * diff * diff : (ad - 0.5f);
    }
    float contrib = ign[p] * s * 0.125f;              // mean over C=8

    #pragma unroll
    for (int off = 16; off; off >>= 1)
        contrib += __shfl_xor_sync(0xFFFFFFFFu, contrib, off);
    if ((tid & 31) == 0) ws[tid >> 5] = contrib;
    __syncthreads();
    if (tid == 0) {
        float tsum = 0.f;
        #pragma unroll
        for (int u = 0; u < 8; u++) tsum += ws[u];
        g_part[bx] = tsum;
        __threadfence();
        unsigned t = atomicAdd(&g_done, 1u);
        s_last = (((t + 1u) & (NBLK - 1u)) == 0u);    // last arrival this replay
    }
    __syncthreads();

    // ================= Phase 4: last block does deterministic reduction ======
    if (s_last) {
        __threadfence();
        float v = 0.f;
        if (tid < NBLK) {
            v = __ldcg(&g_part[tid]);                  // bypass L1 (cross-SM data)
            #pragma unroll
            for (int off = 16; off; off >>= 1)
                v += __shfl_xor_sync(0xFFFFFFFFu, v, off);
            if ((tid & 31) == 0) ws[tid >> 5] = v;
        }
        __syncthreads();
        if (tid == 0)
            out[0] = ((ws[0] + ws[1]) + (ws[2] + ws[3])) * (1.f / (float)(NB * NPIX));
    }
}

extern "C" void kernel_launch(void* const* d_in, const int* in_sizes, int n_in,
                              void* d_out, int out_size)
{
    const float* pred = (const float*)d_in[0];   // [2,8,128,128] f32
    const int*   mask = (const int*)  d_in[1];   // [2,128,128]   i32
    const float* ign  = (const float*)d_in[2];   // [2,128,128]   f32
    float* out = (float*)d_out;                  // [0]=loss, [1..]=gt

    fused_kernel<<<NBLK, TPB>>>(pred, mask, ign, out);
}

// round 4
// speedup vs baseline: 1.9474x; 1.0226x over previous
#include <cuda_runtime.h>

#define WH    128
#define NPIX  (WH*WH)      // 16384
#define NB    2
#define NBK   32           // 2 batches x 16 instances
#define NBLK  128          // persistent grid (all co-resident on 148 SMs)
#define TPB   256

// Scratch (no allocations allowed)
__device__ float    g_rm2[NB * NPIX];    // per-pixel own-label vertical dist^2 (128KB)
__device__ unsigned g_max[NBK];          // per-(b,k) max(d) as ordered uint
__device__ float    g_part[NBLK];        // per-block loss partials
__device__ unsigned g_count = 0;         // monotonic grid-barrier ticket counter
__device__ unsigned g_done  = 0;         // monotonic arrival counter (final reduce)

// Grid-wide barrier: monotonic ticket counter, safe across graph replays.
__device__ __forceinline__ void gridbar()
{
    __threadfence();
    __syncthreads();
    if (threadIdx.x == 0) {
        unsigned ticket = atomicAdd(&g_count, 1u) + 1u;
        unsigned target = ((ticket + NBLK - 1u) / NBLK) * NBLK;
        volatile unsigned* vc = &g_count;
        while (*vc < target) { }              // tight spin: lowest wake latency
    }
    __syncthreads();
    __threadfence();
}

__global__ __launch_bounds__(TPB, 1) void fused_kernel(
    const float* __restrict__ pred,
    const int*   __restrict__ mask,
    const float* __restrict__ ign,
    float* __restrict__ out)
{
    const int tid = threadIdx.x;
    const int bx  = blockIdx.x;

    __shared__ float    s_rm2[2][WH];
    __shared__ int      s_lab[2][WH];
    __shared__ int      s_m31[2][4], s_m0[2][4];
    __shared__ int      s_L[2][4],   s_M[2][4];
    __shared__ unsigned smax[16];
    __shared__ float    ws[8];
    __shared__ int      s_last;

    // ---- Pixel mapping for phases 2/3 (row-major) + early prefetch ----------
    const int p  = bx * TPB + tid;            // pixel id 0..32767
    const int b  = p >> 14;
    const int xy = p & (NPIX - 1);
    const int j  = xy & 127;
    const int r0 = tid >> 7;                  // which of the block's 2 rows
    const int base_i = (bx & 63) * 2;

    // Prefetch pred (8 strided, lane-coalesced) + ign: fully independent of
    // phases 1-2, so these DRAM/L2 round trips hide under the compute+barriers.
    const float* pp = pred + b * 8 * NPIX + xy;
    float pr[8];
    #pragma unroll
    for (int c = 0; c < 8; c++) pr[c] = pp[c * NPIX];
    const float w_ign = ign[p];

    // ================= Phase 1: per-pixel vertical run distance ==============
    // rm2[b,i,j] = (min dist to nearest different-label pixel above/below)^2,
    // 1e9 if whole column is one label. Warp spans 32 consecutive i of one
    // column; run lengths via ballot + clz/ffs; 4-segment carry fixup.
    {
        const int q    = p;                   // reuse id, column-major decode
        const int bq   = q >> 14;
        const int rem  = q & (NPIX - 1);
        const int jq   = rem >> 7;
        const int iq   = rem & 127;
        const int lane = tid & 31;
        const int w    = (tid >> 5) & 3;
        const int col  = tid >> 7;

        if (bx == 0 && tid < 32) g_max[tid] = 0u;   // reset maxima (bar follows)

        const int m = mask[bq * NPIX + iq * WH + jq];
        if (lane == 31) s_m31[col][w] = m;
        if (lane == 0)  s_m0[col][w]  = m;
        __syncthreads();

        int mprev = __shfl_up_sync(0xFFFFFFFFu, m, 1);
        if (lane == 0)  mprev = (w > 0) ? s_m31[col][w - 1] : -1;
        int mnext = __shfl_down_sync(0xFFFFFFFFu, m, 1);
        if (lane == 31) mnext = (w < 3) ? s_m0[col][w + 1] : -1;

        const bool e  = (iq > 0)   && (m == mprev);
        const bool eb = (iq < 127) && (m == mnext);
        const unsigned z  = ~__ballot_sync(0xFFFFFFFFu, e);
        const unsigned zv = ~__ballot_sync(0xFFFFFFFFu, eb);

        if (lane == 0) {
            s_L[col][w] = z  ? (__clz(z) + 1) : -1;
            s_M[col][w] = zv ? __ffs((int)zv) : -1;
        }
        __syncthreads();
        if (tid < 2) {
            int L = s_L[tid][0];
            for (int u = 1; u < 4; u++) { int lv = s_L[tid][u]; L = (lv < 0) ? L + 32 : lv; s_L[tid][u] = L; }
            int M = s_M[tid][3];
            for (int u = 2; u >= 0; u--) { int mv = s_M[tid][u]; M = (mv < 0) ? M + 32 : mv; s_M[tid][u] = M; }
        }
        __syncthreads();

        const unsigned zb  = z  & (0xFFFFFFFFu >> (31 - lane));
        const unsigned zb2 = zv & (0xFFFFFFFFu << lane);
        const int cprev = s_L[col][(w > 0) ? w - 1 : 0];
        const int cnext = s_M[col][(w < 3) ? w + 1 : 3];
        const int r  = zb  ? (lane - (31 - __clz(zb)) + 1) : (lane + 1 + cprev);
        const int rb = zb2 ? (__ffs((int)zb2) - lane)      : (32 - lane + cnext);

        const int fw = (r  == iq + 1)   ? 1000 : r;
        const int bw = (rb == 128 - iq) ? 1000 : rb;
        const int md = min(fw, bw);
        g_rm2[bq * NPIX + iq * WH + jq] = (md >= WH) ? 1e9f : (float)(md * md);
    }

    gridbar();

    // ================= Phase 2: adaptive row envelope + per-(b,k) max ========
    // d(p)^2 = min_{j'} v[j'] + (j-j')^2 with v[j'] = (lab'==lab ? rm2' : 0).
    // Expanding ring with bit-exact warp-uniform cutoff: once o^2 >= m for all
    // lanes, farther offsets cannot improve (v >= 0, RN monotone).
    {
        const int rr = tid >> 7, jp = tid & 127;
        const int gidx = b * NPIX + (base_i + rr) * WH + jp;
        s_lab[rr][jp] = mask[gidx];
        s_rm2[rr][jp] = g_rm2[gidx];
    }
    if (tid < 16) smax[tid] = 0u;
    __syncthreads();

    const int lab = s_lab[r0][j];
    float d = 0.f;
    int bk = 0;
    {
        float m = (lab > 0) ? s_rm2[r0][j] : 0.f;   // o = 0 term (own pixel)
        for (int o = 1; o < WH; o++) {
            float o2 = (float)(o * o);              // exact integer
            if (__all_sync(0xFFFFFFFFu, o2 >= m)) break;
            int jl = j - o, jr = j + o;
            if (jl >= 0) {
                float v = (s_lab[r0][jl] == lab) ? s_rm2[r0][jl] : 0.f;
                m = fminf(m, o2 + v);
            }
            if (jr < WH) {
                float v = (s_lab[r0][jr] == lab) ? s_rm2[r0][jr] : 0.f;
                m = fminf(m, o2 + v);
            }
        }
        if (lab > 0) {
            bk = (b << 4) + lab - 1;
            d = __fsqrt_rn(m);                      // IEEE sqrt
            atomicMax(&smax[lab - 1], __float_as_uint(d));  // d>=0: uint order ok
        }
    }
    __syncthreads();
    if (tid < 16 && smax[tid]) atomicMax(&g_max[(b << 4) + tid], smax[tid]);

    // ---- Pre-barrier: both smooth-L1 candidates per channel (g=0 and g=1) ---
    float l1a[8], l1b[8];
    #pragma unroll
    for (int c = 0; c < 8; c++) {
        float da = pr[c];                 // diff for g=0
        float aa = fabsf(da);
        l1a[c] = (aa < 1.f) ? 0.5f * da * da : (aa - 0.5f);
        float db = pr[c] - 1.f;           // diff for g=1
        float ab = fabsf(db);
        l1b[c] = (ab < 1.f) ? 0.5f * db * db : (ab - 0.5f);
    }

    gridbar();

    // ================= Phase 3: bin + gt write + loss =========================
    int c0 = -1;
    if (lab > 0) {
        float mv = __uint_as_float(g_max[bk]);
        float dn = (mv > 0.f) ? __fdiv_rn(d, mv) : d;   // IEEE div (bin-exact)
        if (dn < 0.5f) dn = 0.0f;
        if (dn > 0.7f) dn = 1.0f;
        const float DDD[8] = {0.83f, 0.68f, 0.54f, 0.41f, 0.29f, 0.18f, 0.09f, 0.0f};
        c0 = 7;
        #pragma unroll
        for (int c = 0; c < 8; c++)
            if (dn >= DDD[c]) { c0 = c; break; }
    }

    float* go = out + 1 + b * 8 * NPIX + xy;            // out[0] = loss
    float s = 0.f;
    #pragma unroll
    for (int c = 0; c < 8; c++) {
        bool hit = (c == c0);
        go[c * NPIX] = hit ? 1.f : 0.f;
        s += hit ? l1b[c] : l1a[c];                     // same terms, same order
    }
    float contrib = w_ign * s * 0.125f;                 // mean over C=8

    #pragma unroll
    for (int off = 16; off; off >>= 1)
        contrib += __shfl_xor_sync(0xFFFFFFFFu, contrib, off);
    if ((tid & 31) == 0) ws[tid >> 5] = contrib;
    __syncthreads();
    if (tid == 0) {
        float tsum = 0.f;
        #pragma unroll
        for (int u = 0; u < 8; u++) tsum += ws[u];
        g_part[bx] = tsum;
        __threadfence();
        unsigned t = atomicAdd(&g_done, 1u);
        s_last = (((t + 1u) & (NBLK - 1u)) == 0u);      // last arrival this replay
    }
    __syncthreads();

    // ================= Phase 4: last block deterministic reduction ===========
    if (s_last) {
        __threadfence();
        float v = 0.f;
        if (tid < NBLK) {
            v = __ldcg(&g_part[tid]);
            #pragma unroll
            for (int off = 16; off; off >>= 1)
                v += __shfl_xor_sync(0xFFFFFFFFu, v, off);
            if ((tid & 31) == 0) ws[tid >> 5] = v;
        }
        __syncthreads();
        if (tid == 0)
            out[0] = ((ws[0] + ws[1]) + (ws[2] + ws[3])) * (1.f / (float)(NB * NPIX));
    }
}

extern "C" void kernel_launch(void* const* d_in, const int* in_sizes, int n_in,
                              void* d_out, int out_size)
{
    const float* pred = (const float*)d_in[0];   // [2,8,128,128] f32
    const int*   mask = (const int*)  d_in[1];   // [2,128,128]   i32
    const float* ign  = (const float*)d_in[2];   // [2,128,128]   f32
    float* out = (float*)d_out;                  // [0]=loss, [1..]=gt

    fused_kernel<<<NBLK, TPB>>>(pred, mask, ign, out);
}

// round 5
// speedup vs baseline: 2.3125x; 1.1875x over previous
#include <cuda_runtime.h>

#define WH    128
#define NPIX  (WH*WH)      // 16384
#define NB    2
#define NBK   32           // 2 batches x 16 instances
#define NBLK  128          // persistent grid (all co-resident on 148 SMs)
#define TPB   256

// Scratch (no allocations allowed)
__device__ unsigned g_max[NBK];          // per-(b,k) max(d) as ordered uint (reset by last block)
__device__ float    g_part[NBLK];        // per-block loss partials
__device__ unsigned g_count = 0;         // monotonic grid-barrier ticket counter
__device__ unsigned g_done  = 0;         // monotonic arrival counter (final reduce)

// Grid-wide barrier: monotonic ticket counter, safe across graph replays.
__device__ __forceinline__ void gridbar()
{
    __threadfence();
    __syncthreads();
    if (threadIdx.x == 0) {
        unsigned ticket = atomicAdd(&g_count, 1u) + 1u;
        unsigned target = ((ticket + NBLK - 1u) / NBLK) * NBLK;
        volatile unsigned* vc = &g_count;
        while (*vc < target) { }
    }
    __syncthreads();
    __threadfence();
}

__global__ __launch_bounds__(TPB, 1) void fused_kernel(
    const float* __restrict__ pred,
    const int*   __restrict__ mask,
    const float* __restrict__ ign,
    float* __restrict__ out)
{
    const int tid = threadIdx.x;
    const int bx  = blockIdx.x;

    const int p  = bx * TPB + tid;        // pixel id 0..32767 (row-major)
    const int b  = p >> 14;               // batch (64 blocks per batch)
    const int xy = p & (NPIX - 1);
    const int i0 = xy >> 7;               // this pixel's row
    const int j  = xy & 127;
    const int r0 = tid >> 7;              // 0/1: which of the block's 2 rows

    __shared__ unsigned char s_mask[NPIX];     // 16KB: whole batch mask as bytes
    __shared__ float    s_rm2[2][WH];
    __shared__ unsigned smax[16];
    __shared__ float    s_gm[16];
    __shared__ float    ws[8];
    __shared__ int      s_last;

    // ---- Early prefetch (independent of everything; hides DRAM/L2 latency) --
    const float* pp = pred + b * 8 * NPIX + xy;
    float pr[8];
    #pragma unroll
    for (int c = 0; c < 8; c++) pr[c] = pp[c * NPIX];
    const float w_ign = ign[p];

    // ---- Load this batch's full mask into shared as bytes (int4-coalesced) --
    {
        const int4* m4 = (const int4*)(mask + b * NPIX);   // 4096 int4
        #pragma unroll
        for (int k = 0; k < 16; k++) {
            int idx = tid + k * TPB;
            int4 v = m4[idx];
            unsigned packed = (unsigned)v.x | ((unsigned)v.y << 8) |
                              ((unsigned)v.z << 16) | ((unsigned)v.w << 24);
            ((unsigned*)s_mask)[idx] = packed;
        }
    }
    if (tid < 16) smax[tid] = 0u;
    __syncthreads();

    const int lab = s_mask[xy];

    // ---- rm2 at own pixel: vertical same-label run distance^2 (local scan) --
    // du/dd = distance to nearest different-label pixel above/below (1000=none)
    {
        int ru = 0;
        while (i0 - 1 - ru >= 0 && s_mask[(i0 - 1 - ru) * WH + j] == lab) ru++;
        const int du = (i0 - 1 - ru >= 0) ? ru + 1 : 1000;
        int rd = 0;
        while (i0 + 1 + rd < WH && s_mask[(i0 + 1 + rd) * WH + j] == lab) rd++;
        const int dd = (i0 + 1 + rd < WH) ? rd + 1 : 1000;
        const int md = min(du, dd);
        s_rm2[r0][j] = (md >= WH) ? 1e9f : (float)(md * md);
    }
    __syncthreads();

    // ---- Adaptive row envelope (bit-exact early cutoff) + per-(b,k) max ----
    // d^2 = min_{j'} v[j'] + (j-j')^2, v[j'] = (lab'==lab ? rm2[j'] : 0) >= 0.
    // Once o^2 >= m for all lanes, farther offsets cannot improve (RN monotone).
    float d = 0.f;
    int   bk = 0;
    {
        const int rowbase = i0 * WH;
        float m = (lab > 0) ? s_rm2[r0][j] : 0.f;          // o = 0 term
        for (int o = 1; o < WH; o++) {
            float o2 = (float)(o * o);                     // exact integer
            if (__all_sync(0xFFFFFFFFu, o2 >= m)) break;
            int jl = j - o, jr = j + o;
            if (jl >= 0) {
                float v = (s_mask[rowbase + jl] == lab) ? s_rm2[r0][jl] : 0.f;
                m = fminf(m, o2 + v);
            }
            if (jr < WH) {
                float v = (s_mask[rowbase + jr] == lab) ? s_rm2[r0][jr] : 0.f;
                m = fminf(m, o2 + v);
            }
        }
        if (lab > 0) {
            bk = (b << 4) + lab - 1;
            d = __fsqrt_rn(m);                              // IEEE sqrt
            atomicMax(&smax[lab - 1], __float_as_uint(d));  // d>=0: uint order ok
        }
    }
    __syncthreads();
    if (tid < 16 && smax[tid]) atomicMax(&g_max[(b << 4) + tid], smax[tid]);

    // ---- Pre-barrier: both smooth-L1 candidates per channel (g=0 / g=1) ----
    float l1a[8], l1b[8];
    #pragma unroll
    for (int c = 0; c < 8; c++) {
        float da = pr[c];
        float aa = fabsf(da);
        l1a[c] = (aa < 1.f) ? 0.5f * da * da : (aa - 0.5f);
        float db = pr[c] - 1.f;
        float ab = fabsf(db);
        l1b[c] = (ab < 1.f) ? 0.5f * db * db : (ab - 0.5f);
    }

    gridbar();   // the only global sync: per-(b,k) maxima must be final

    // ---- Stage final maxima for this batch --------------------------------
    if (tid < 16) s_gm[tid] = __uint_as_float(__ldcg(&g_max[(b << 4) + tid]));
    __syncthreads();

    // ---- Bin select + gt write + loss --------------------------------------
    int c0 = -1;
    if (lab > 0) {
        float mv = s_gm[lab - 1];
        float dn = (mv > 0.f) ? __fdiv_rn(d, mv) : d;      // IEEE div
        if (dn < 0.5f) dn = 0.0f;
        if (dn > 0.7f) dn = 1.0f;
        const float DDD[8] = {0.83f, 0.68f, 0.54f, 0.41f, 0.29f, 0.18f, 0.09f, 0.0f};
        c0 = 7;
        #pragma unroll
        for (int c = 0; c < 8; c++)
            if (dn >= DDD[c]) { c0 = c; break; }
    }

    float* go = out + 1 + b * 8 * NPIX + xy;               // out[0] = loss
    float s = 0.f;
    #pragma unroll
    for (int c = 0; c < 8; c++) {
        bool hit = (c == c0);
        go[c * NPIX] = hit ? 1.f : 0.f;
        s += hit ? l1b[c] : l1a[c];                        // same terms, same order
    }
    float contrib = w_ign * s * 0.125f;                    // mean over C=8

    #pragma unroll
    for (int off = 16; off; off >>= 1)
        contrib += __shfl_xor_sync(0xFFFFFFFFu, contrib, off);
    if ((tid & 31) == 0) ws[tid >> 5] = contrib;
    __syncthreads();
    if (tid == 0) {
        float tsum = 0.f;
        #pragma unroll
        for (int u = 0; u < 8; u++) tsum += ws[u];
        g_part[bx] = tsum;
        __threadfence();
        unsigned t = atomicAdd(&g_done, 1u);
        s_last = (((t + 1u) & (NBLK - 1u)) == 0u);         // last arrival this replay
    }
    __syncthreads();

    // ---- Last block: reset maxima for next replay + deterministic reduction -
    // Safe: every block's g_max reads happen-before its g_done increment
    // (program order + threadfence), and we only get here after all 128.
    if (s_last) {
        __threadfence();
        if (tid < NBK) g_max[tid] = 0u;
        float v = 0.f;
        if (tid < NBLK) {
            v = __ldcg(&g_part[tid]);
            #pragma unroll
            for (int off = 16; off; off >>= 1)
                v += __shfl_xor_sync(0xFFFFFFFFu, v, off);
            if ((tid & 31) == 0) ws[tid >> 5] = v;
        }
        __syncthreads();
        if (tid == 0)
            out[0] = ((ws[0] + ws[1]) + (ws[2] + ws[3])) * (1.f / (float)(NB * NPIX));
    }
}

extern "C" void kernel_launch(void* const* d_in, const int* in_sizes, int n_in,
                              void* d_out, int out_size)
{
    const float* pred = (const float*)d_in[0];   // [2,8,128,128] f32
    const int*   mask = (const int*)  d_in[1];   // [2,128,128]   i32
    const float* ign  = (const float*)d_in[2];   // [2,128,128]   f32
    float* out = (float*)d_out;                  // [0]=loss, [1..]=gt

    fused_kernel<<<NBLK, TPB>>>(pred, mask, ign, out);
}

// round 6
// speedup vs baseline: 2.3194x; 1.0030x over previous
#include <cuda_runtime.h>

#define WH    128
#define NPIX  (WH*WH)      // 16384
#define NB    2
#define NBK   32           // 2 batches x 16 instances
#define NBLK  64           // persistent grid (all co-resident)
#define TPB   512          // 4 rows per block

// Scratch (no allocations allowed)
__device__ unsigned g_max[NBK];          // per-(b,k) max(d) as ordered uint (reset by last block)
__device__ float    g_part[NBLK];        // per-block loss partials
__device__ unsigned g_count = 0;         // monotonic grid-barrier ticket counter
__device__ unsigned g_done  = 0;         // monotonic arrival counter (final reduce)

// Grid-wide barrier: monotonic ticket counter, safe across graph replays.
__device__ __forceinline__ void gridbar()
{
    __threadfence();
    __syncthreads();
    if (threadIdx.x == 0) {
        unsigned ticket = atomicAdd(&g_count, 1u) + 1u;
        unsigned target = ((ticket + NBLK - 1u) / NBLK) * NBLK;
        volatile unsigned* vc = &g_count;
        while (*vc < target) { }
    }
    __syncthreads();
    __threadfence();
}

__global__ __launch_bounds__(TPB, 1) void fused_kernel(
    const float* __restrict__ pred,
    const int*   __restrict__ mask,
    const float* __restrict__ ign,
    float* __restrict__ out)
{
    const int tid = threadIdx.x;
    const int bx  = blockIdx.x;

    const int p  = bx * TPB + tid;        // pixel id 0..32767 (row-major)
    const int b  = p >> 14;               // batch (32 blocks per batch)
    const int xy = p & (NPIX - 1);
    const int i0 = xy >> 7;               // this pixel's row
    const int j  = xy & 127;
    const int r0 = tid >> 7;              // 0..3: which of the block's 4 rows

    __shared__ unsigned char s_mask[NPIX];     // 16KB: whole batch mask as bytes
    __shared__ float    s_rm2[4][WH];
    __shared__ unsigned smax[16];
    __shared__ float    s_gm[16];
    __shared__ float    ws[16];
    __shared__ int      s_last;

    // ---- Early prefetch (independent; hides DRAM/L2 latency under compute) --
    const float* pp = pred + b * 8 * NPIX + xy;
    float pr[8];
    #pragma unroll
    for (int c = 0; c < 8; c++) pr[c] = pp[c * NPIX];
    const float w_ign = ign[p];

    // ---- Load this batch's mask into shared as bytes (int4 + 3x prmt) -------
    {
        const int4* m4 = (const int4*)(mask + b * NPIX);   // 4096 int4
        unsigned* sm32 = (unsigned*)s_mask;
        #pragma unroll
        for (int k = 0; k < 8; k++) {
            int idx = tid + k * TPB;
            int4 v = m4[idx];
            unsigned t1 = __byte_perm((unsigned)v.x, (unsigned)v.y, 0x0040);
            unsigned t2 = __byte_perm((unsigned)v.z, (unsigned)v.w, 0x0040);
            sm32[idx] = __byte_perm(t1, t2, 0x5410);       // {x0,y0,z0,w0}
        }
    }
    if (tid < 16) smax[tid] = 0u;
    __syncthreads();

    const int lab = s_mask[xy];

    // ---- rm2 at own pixel: vertical same-label run distance^2 ---------------
    // Batched: 16 independent LDS (8 up, 8 down) -> bitmask -> ffs. Fallback
    // loop only for runs >= 8 (probability ~17^-8). Identical run lengths.
    {
        unsigned upb = 0, dnb = 0;
        #pragma unroll
        for (int t = 1; t <= 8; t++) {
            int iu = i0 - t, idn = i0 + t;
            if (iu >= 0  && s_mask[iu  * WH + j] == lab) upb |= 1u << (t - 1);
            if (idn < WH && s_mask[idn * WH + j] == lab) dnb |= 1u << (t - 1);
        }
        int ru = __ffs(~upb) - 1;                 // leading consecutive matches
        if (ru == 8) { while (i0 - 1 - ru >= 0 && s_mask[(i0 - 1 - ru) * WH + j] == lab) ru++; }
        const int du = (i0 - 1 - ru >= 0) ? ru + 1 : 1000;

        int rd = __ffs(~dnb) - 1;
        if (rd == 8) { while (i0 + 1 + rd < WH && s_mask[(i0 + 1 + rd) * WH + j] == lab) rd++; }
        const int dd = (i0 + 1 + rd < WH) ? rd + 1 : 1000;

        const int md = min(du, dd);
        s_rm2[r0][j] = (md >= WH) ? 1e9f : (float)(md * md);
    }
    __syncthreads();

    // ---- Adaptive row envelope (bit-exact early cutoff) + per-(b,k) max ----
    // d^2 = min_{j'} v[j'] + (j-j')^2, v[j'] = (lab'==lab ? rm2[j'] : 0) >= 0.
    // Pairs of offsets per warp-uniform check: break when o^2 >= m for all
    // lanes at the SMALLER o of the pair (conservative; fminf set-exact).
    float d = 0.f;
    int   bk = 0;
    {
        const int rowbase = i0 * WH;
        float m = (lab > 0) ? s_rm2[r0][j] : 0.f;          // o = 0 term
        for (int o = 1; o < WH; o += 2) {
            float o2a = (float)(o * o);                    // exact integer
            if (__all_sync(0xFFFFFFFFu, o2a >= m)) break;
            int jl = j - o, jr = j + o;
            if (jl >= 0) { float v = (s_mask[rowbase + jl] == lab) ? s_rm2[r0][jl] : 0.f; m = fminf(m, o2a + v); }
            if (jr < WH) { float v = (s_mask[rowbase + jr] == lab) ? s_rm2[r0][jr] : 0.f; m = fminf(m, o2a + v); }
            int o1 = o + 1; float o2b = (float)(o1 * o1);
            int jl1 = j - o1, jr1 = j + o1;
            if (jl1 >= 0) { float v = (s_mask[rowbase + jl1] == lab) ? s_rm2[r0][jl1] : 0.f; m = fminf(m, o2b + v); }
            if (jr1 < WH) { float v = (s_mask[rowbase + jr1] == lab) ? s_rm2[r0][jr1] : 0.f; m = fminf(m, o2b + v); }
        }
        if (lab > 0) {
            bk = (b << 4) + lab - 1;
            d = __fsqrt_rn(m);                              // IEEE sqrt
            atomicMax(&smax[lab - 1], __float_as_uint(d));  // d>=0: uint order ok
        }
    }
    __syncthreads();
    if (tid < 16 && smax[tid]) atomicMax(&g_max[(b << 4) + tid], smax[tid]);

    // ---- Pre-barrier: both smooth-L1 candidates per channel (g=0 / g=1) ----
    float l1a[8], l1b[8];
    #pragma unroll
    for (int c = 0; c < 8; c++) {
        float da = pr[c];
        float aa = fabsf(da);
        l1a[c] = (aa < 1.f) ? 0.5f * da * da : (aa - 0.5f);
        float db = pr[c] - 1.f;
        float ab = fabsf(db);
        l1b[c] = (ab < 1.f) ? 0.5f * db * db : (ab - 0.5f);
    }

    gridbar();   // the only global sync: per-(b,k) maxima must be final

    // ---- Stage final maxima for this batch --------------------------------
    if (tid < 16) s_gm[tid] = __uint_as_float(__ldcg(&g_max[(b << 4) + tid]));
    __syncthreads();

    // ---- Bin select + gt write + loss --------------------------------------
    int c0 = -1;
    if (lab > 0) {
        float mv = s_gm[lab - 1];
        float dn = (mv > 0.f) ? __fdiv_rn(d, mv) : d;      // IEEE div
        if (dn < 0.5f) dn = 0.0f;
        if (dn > 0.7f) dn = 1.0f;
        const float DDD[8] = {0.83f, 0.68f, 0.54f, 0.41f, 0.29f, 0.18f, 0.09f, 0.0f};
        c0 = 7;
        #pragma unroll
        for (int c = 0; c < 8; c++)
            if (dn >= DDD[c]) { c0 = c; break; }
    }

    float* go = out + 1 + b * 8 * NPIX + xy;               // out[0] = loss
    float s = 0.f;
    #pragma unroll
    for (int c = 0; c < 8; c++) {
        bool hit = (c == c0);
        go[c * NPIX] = hit ? 1.f : 0.f;
        s += hit ? l1b[c] : l1a[c];                        // same terms, same order
    }
    float contrib = w_ign * s * 0.125f;                    // mean over C=8

    #pragma unroll
    for (int off = 16; off; off >>= 1)
        contrib += __shfl_xor_sync(0xFFFFFFFFu, contrib, off);
    if ((tid & 31) == 0) ws[tid >> 5] = contrib;
    __syncthreads();
    if (tid == 0) {
        float tsum = 0.f;
        #pragma unroll
        for (int u = 0; u < 16; u++) tsum += ws[u];
        g_part[bx] = tsum;
        __threadfence();
        unsigned t = atomicAdd(&g_done, 1u);
        s_last = (((t + 1u) & (NBLK - 1u)) == 0u);         // last arrival this replay
    }
    __syncthreads();

    // ---- Last block: reset maxima for next replay + deterministic reduction -
    if (s_last) {
        __threadfence();
        if (tid < NBK) g_max[tid] = 0u;
        float v = 0.f;
        if (tid < NBLK) {
            v = __ldcg(&g_part[tid]);
            #pragma unroll
            for (int off = 16; off; off >>= 1)
                v += __shfl_xor_sync(0xFFFFFFFFu, v, off);
            if ((tid & 31) == 0) ws[tid >> 5] = v;
        }
        __syncthreads();
        if (tid == 0)
            out[0] = (ws[0] + ws[1]) * (1.f / (float)(NB * NPIX));
    }
}

extern "C" void kernel_launch(void* const* d_in, const int* in_sizes, int n_in,
                              void* d_out, int out_size)
{
    const float* pred = (const float*)d_in[0];   // [2,8,128,128] f32
    const int*   mask = (const int*)  d_in[1];   // [2,128,128]   i32
    const float* ign  = (const float*)d_in[2];   // [2,128,128]   f32
    float* out = (float*)d_out;                  // [0]=loss, [1..]=gt

    fused_kernel<<<NBLK, TPB>>>(pred, mask, ign, out);
}